// round 10
// baseline (speedup 1.0000x reference)
#include <cuda_runtime.h>
#include <cuda_fp16.h>
#include <cstdint>
#include <math.h>

#define BATCH 4096
#define NCLS  256
#define NDIM  256

#define MT 32                  // batch rows per CTA
#define NSTAGES 24             // logical K stages of 64 halves
#define NBUF 5
#define B_BYTES 32768          // 256 classes x 64 halves
#define A_OFF   (NBUF * B_BYTES)          // 163840
#define A_BYTES (MT * 1024 * 2)           // 64KB  (phys K=1024 per row)
#define SMEM_TOTAL (A_OFF + A_BYTES)      // 224KB

// W phys layout per class row (K=1024): [w1_hi|w2_hi|w1_lo|w2_lo] (256 each)
__device__ __align__(16) __half g_w[NCLS * 1024];      // 512KB
__device__ __align__(16) float  g_bias[NCLS];

// ---------------------------------------------------------------------------
__device__ __forceinline__ unsigned smem_u32(const void* p) {
    return (unsigned)__cvta_generic_to_shared(p);
}
__device__ __forceinline__ unsigned pack2(__half lo, __half hi) {
    return (unsigned)__half_as_ushort(lo) | ((unsigned)__half_as_ushort(hi) << 16);
}

#define LDSM_X4(r0, r1, r2, r3, addr) \
    asm volatile("ldmatrix.sync.aligned.m8n8.x4.shared.b16 {%0,%1,%2,%3}, [%4];" \
                 : "=r"(r0), "=r"(r1), "=r"(r2), "=r"(r3) : "r"(addr))

#define MMA16816(d, a0, a1, a2, a3, b0, b1) \
    asm volatile("mma.sync.aligned.m16n8k16.row.col.f32.f16.f16.f32 " \
                 "{%0,%1,%2,%3}, {%4,%5,%6,%7}, {%8,%9}, {%0,%1,%2,%3};" \
                 : "+f"((d)[0]), "+f"((d)[1]), "+f"((d)[2]), "+f"((d)[3]) \
                 : "r"(a0), "r"(a1), "r"(a2), "r"(a3), "r"(b0), "r"(b1))

// ---------------------------------------------------------------------------
// prep_w: one block per class; phys K=1024 layout + bias
// ---------------------------------------------------------------------------
__global__ void prep_w_kernel(const float* __restrict__ centers,
                              const float* __restrict__ Droot) {
    int k = blockIdx.x;
    int d = threadIdx.x;
    int idx = k * NDIM + d;

    float D    = fabsf(Droot[idx]) + 1e-4f;
    float dinv = 1.0f / D;
    float c    = centers[idx];

    float w1 = -0.5f * dinv;
    float w2 = c * dinv;
    __half w1h = __float2half_rn(w1);
    __half w1l = __float2half_rn(w1 - __half2float(w1h));
    __half w2h = __float2half_rn(w2);
    __half w2l = __float2half_rn(w2 - __half2float(w2h));

    __half* row = g_w + (size_t)k * 1024;
    row[d]       = w1h;
    row[256 + d] = w2h;
    row[512 + d] = w1l;
    row[768 + d] = w2l;

    float p = c * c * dinv + logf(D);
    __shared__ float red[8];
    #pragma unroll
    for (int o = 16; o; o >>= 1) p += __shfl_xor_sync(0xFFFFFFFFu, p, o);
    if ((threadIdx.x & 31) == 0) red[threadIdx.x >> 5] = p;
    __syncthreads();
    if (threadIdx.x < 8) {
        float v = red[threadIdx.x];
        #pragma unroll
        for (int o = 4; o; o >>= 1) v += __shfl_xor_sync(0xFFu, v, o);
        if (threadIdx.x == 0) g_bias[k] = -0.5f * v;
    }
}

// ---------------------------------------------------------------------------
// Logical stage s -> phys stage (of 64 halves):
//   A (phi): s<16 -> s;  s>=16 -> s-16 (hi again)
//   B (W):   s<8  -> s;  s>=8  -> s-8  (hi again for 8..15, lo for 16..23)
// ---------------------------------------------------------------------------
__device__ __forceinline__ int a_phys(int s) { return s < 16 ? s : s - 16; }
__device__ __forceinline__ int b_phys(int s) { return s < 8 ? s : s - 8; }

__device__ __forceinline__ void issue_b_stage(unsigned char* sm, int t, int s) {
    unsigned bbase = smem_u32(sm + (s % NBUF) * B_BYTES);
    const int bk = b_phys(s) * 64;
    const int j  = t & 7;
    #pragma unroll
    for (int i = 0; i < 8; i++) {
        int k = (t >> 3) + 32 * i;
        unsigned dst = bbase + k * 128 + ((unsigned)(j ^ (k & 7)) << 4);
        const __half* src = g_w + (size_t)k * 1024 + bk + j * 8;
        asm volatile("cp.async.cg.shared.global [%0], [%1], 16;" :: "r"(dst), "l"(src));
    }
    asm volatile("cp.async.commit_group;");
}

__global__ __launch_bounds__(256, 1) void gmm_fused_kernel(
        const float* __restrict__ x, float* __restrict__ out) {
    extern __shared__ __align__(128) unsigned char sm[];
    const int t    = threadIdx.x;
    const int lane = t & 31;
    const int wid  = t >> 5;
    const int b0   = blockIdx.x * MT;

    // ---- prologue: start B pipeline (4 deep), convert x -> phi in smem A ----
    issue_b_stage(sm, t, 0);
    issue_b_stage(sm, t, 1);
    issue_b_stage(sm, t, 2);
    issue_b_stage(sm, t, 3);

    {
        // thread: row r = t>>3, dims [seg*32, seg*32+32)
        const int r   = t >> 3;
        const int seg = t & 7;
        const float* xr = x + (size_t)(b0 + r) * NDIM + seg * 32;
        unsigned arow = smem_u32(sm + A_OFF) + r * 2048;
        const unsigned rs = (unsigned)(r & 7);
        #pragma unroll
        for (int c = 0; c < 4; c++) {
            float4 xa = *(const float4*)(xr + c * 8);
            float4 xb = *(const float4*)(xr + c * 8 + 4);
            float v[8] = {xa.x, xa.y, xa.z, xa.w, xb.x, xb.y, xb.z, xb.w};
            __half x2h[8], x2l[8], xh[8], xl[8];
            #pragma unroll
            for (int e = 0; e < 8; e++) {
                float a = v[e] * v[e];
                x2h[e] = __float2half_rn(a);
                x2l[e] = __float2half_rn(a - __half2float(x2h[e]));
                xh[e]  = __float2half_rn(v[e]);
                xl[e]  = __float2half_rn(v[e] - __half2float(xh[e]));
            }
            const int db = seg * 32 + c * 8;
            const __half* regs[4] = {x2h, xh, x2l, xl};
            #pragma unroll
            for (int Rg = 0; Rg < 4; Rg++) {
                int p0 = Rg * 256 + db;
                int ks = p0 >> 6;
                unsigned j = (unsigned)((p0 >> 3) & 7);
                unsigned addr = arow + ks * 128 + ((j ^ rs) << 4);
                const __half* h = regs[Rg];
                unsigned p0w = pack2(h[0], h[1]);
                unsigned p1w = pack2(h[2], h[3]);
                unsigned p2w = pack2(h[4], h[5]);
                unsigned p3w = pack2(h[6], h[7]);
                asm volatile("st.shared.v4.b32 [%0], {%1,%2,%3,%4};"
                             :: "r"(addr), "r"(p0w), "r"(p1w), "r"(p2w), "r"(p3w));
            }
        }
    }

    // ---- precomputed per-thread ldmatrix offsets (stage-invariant) ----
    unsigned offa[2][4], offb[2][4];
    {
        const int arow = lane & 15;
        const int akh  = lane >> 4;
        const int brow = wid * 32 + (lane & 7) + ((lane >> 4) & 1) * 8;
        const int bkh  = (lane >> 3) & 1;
        #pragma unroll
        for (int ks = 0; ks < 4; ks++) {
            #pragma unroll
            for (int mt = 0; mt < 2; mt++) {
                int r = arow + mt * 16;
                offa[mt][ks] = (unsigned)(r * 2048) +
                               ((unsigned)((ks * 2 + akh) ^ (r & 7)) << 4);
            }
            #pragma unroll
            for (int np = 0; np < 2; np++) {
                int r = brow + np * 16;
                offb[np][ks] = (unsigned)(r * 128) +
                               ((unsigned)((ks * 2 + bkh) ^ (r & 7)) << 4);
            }
        }
    }

    float d[2][4][4];
    #pragma unroll
    for (int mt = 0; mt < 2; mt++)
        #pragma unroll
        for (int nt = 0; nt < 4; nt++)
            #pragma unroll
            for (int e = 0; e < 4; e++) d[mt][nt][e] = 0.0f;

    const unsigned abase0 = smem_u32(sm + A_OFF);

    for (int s = 0; s < NSTAGES; s++) {
        if (s < NSTAGES - 3)       asm volatile("cp.async.wait_group 3;");
        else if (s == NSTAGES - 3) asm volatile("cp.async.wait_group 2;");
        else if (s == NSTAGES - 2) asm volatile("cp.async.wait_group 1;");
        else                       asm volatile("cp.async.wait_group 0;");
        __syncthreads();   // stage s ready; orders refill below vs stage s-1 reads

        // refill buffer consumed at stage s-1, overlapping this stage's compute
        if (s + 4 < NSTAGES) issue_b_stage(sm, t, s + 4);

        unsigned bbase = smem_u32(sm + (s % NBUF) * B_BYTES);
        unsigned abase = abase0 + (unsigned)(a_phys(s) * 128);

        #pragma unroll
        for (int ks = 0; ks < 4; ks++) {
            unsigned a[2][4], b[2][4];
            #pragma unroll
            for (int mt = 0; mt < 2; mt++)
                LDSM_X4(a[mt][0], a[mt][1], a[mt][2], a[mt][3], abase + offa[mt][ks]);
            #pragma unroll
            for (int np = 0; np < 2; np++)
                LDSM_X4(b[np][0], b[np][1], b[np][2], b[np][3], bbase + offb[np][ks]);
            #pragma unroll
            for (int mt = 0; mt < 2; mt++)
                #pragma unroll
                for (int nt = 0; nt < 4; nt++) {
                    int np = nt >> 1, off = (nt & 1) * 2;
                    MMA16816(d[mt][nt], a[mt][0], a[mt][1], a[mt][2], a[mt][3],
                             b[np][off], b[np][off + 1]);
                }
        }
    }

    // ---- epilogue: logits (+bias) into smem (reuse B buffers), softmax ----
    float* ls = (float*)sm;   // 32 rows x 256 cols f32 = 32KB
    __syncthreads();
    #pragma unroll
    for (int mt = 0; mt < 2; mt++) {
        int row = mt * 16 + (lane >> 2);
        #pragma unroll
        for (int nt = 0; nt < 4; nt++) {
            int col = wid * 32 + nt * 8 + (lane & 3) * 2;
            float2 bv = *(const float2*)(g_bias + col);
            float2 v0 = {d[mt][nt][0] + bv.x, d[mt][nt][1] + bv.y};
            float2 v1 = {d[mt][nt][2] + bv.x, d[mt][nt][3] + bv.y};
            *(float2*)(ls + row * NCLS + col)       = v0;
            *(float2*)(ls + (row + 8) * NCLS + col) = v1;
        }
    }
    __syncthreads();

    #pragma unroll
    for (int rr = 0; rr < 4; rr++) {
        int r = wid * 4 + rr;
        const float4* lrow = (const float4*)(ls + r * NCLS);
        float4 a = lrow[lane * 2];
        float4 b = lrow[lane * 2 + 1];

        float mx = fmaxf(fmaxf(fmaxf(a.x, a.y), fmaxf(a.z, a.w)),
                         fmaxf(fmaxf(b.x, b.y), fmaxf(b.z, b.w)));
        #pragma unroll
        for (int o = 16; o; o >>= 1) mx = fmaxf(mx, __shfl_xor_sync(0xFFFFFFFFu, mx, o));

        float4 ea, eb;
        ea.x = __expf(a.x - mx); ea.y = __expf(a.y - mx);
        ea.z = __expf(a.z - mx); ea.w = __expf(a.w - mx);
        eb.x = __expf(b.x - mx); eb.y = __expf(b.y - mx);
        eb.z = __expf(b.z - mx); eb.w = __expf(b.w - mx);

        float sum = (ea.x + ea.y) + (ea.z + ea.w) + (eb.x + eb.y) + (eb.z + eb.w);
        #pragma unroll
        for (int o = 16; o; o >>= 1) sum += __shfl_xor_sync(0xFFFFFFFFu, sum, o);

        float inv = 1.0f / sum;
        ea.x *= inv; ea.y *= inv; ea.z *= inv; ea.w *= inv;
        eb.x *= inv; eb.y *= inv; eb.z *= inv; eb.w *= inv;

        float4* orow = (float4*)(out + (size_t)(b0 + r) * NCLS);
        orow[lane * 2]     = ea;
        orow[lane * 2 + 1] = eb;
    }
}

// ---------------------------------------------------------------------------
extern "C" void kernel_launch(void* const* d_in, const int* in_sizes, int n_in,
                              void* d_out, int out_size) {
    const float* x       = (const float*)d_in[0];
    const float* centers = (const float*)d_in[1];
    const float* Droot   = (const float*)d_in[2];
    float*       out     = (float*)d_out;

    cudaFuncSetAttribute(gmm_fused_kernel,
                         cudaFuncAttributeMaxDynamicSharedMemorySize, SMEM_TOTAL);

    prep_w_kernel<<<NCLS, NDIM>>>(centers, Droot);
    gmm_fused_kernel<<<BATCH / MT, 256, SMEM_TOTAL>>>(x, out);
}

// round 11
// speedup vs baseline: 1.2054x; 1.2054x over previous
#include <cuda_runtime.h>
#include <cuda_fp16.h>
#include <cstdint>
#include <math.h>

#define BATCH 4096
#define NCLS  256
#define NDIM  256

#define MT 32                    // batch rows per CTA
#define NP 8                     // hi/lo pair iterations
#define PAIR_BYTES 65536         // B_hi stage (32KB) + B_lo stage (32KB)
#define A_OFF   (2 * PAIR_BYTES)            // 131072
#define A_BYTES (MT * 1024 * 2)             // 64KB (phys K=1024 per row)
#define SMEM_TOTAL (A_OFF + A_BYTES)        // 192KB

// W phys layout per class row (K=1024): [w1_hi|w2_hi|w1_lo|w2_lo] (256 each)
// -> 16 chunk-stages of 64 halves; stage p = hi dims, stage p+8 = lo dims
__device__ __align__(16) __half g_w[NCLS * 1024];      // 512KB
__device__ __align__(16) float  g_bias[NCLS];

// ---------------------------------------------------------------------------
__device__ __forceinline__ unsigned smem_u32(const void* p) {
    return (unsigned)__cvta_generic_to_shared(p);
}
__device__ __forceinline__ unsigned pack2(__half lo, __half hi) {
    return (unsigned)__half_as_ushort(lo) | ((unsigned)__half_as_ushort(hi) << 16);
}

#define LDSM_X4(r0, r1, r2, r3, addr) \
    asm volatile("ldmatrix.sync.aligned.m8n8.x4.shared.b16 {%0,%1,%2,%3}, [%4];" \
                 : "=r"(r0), "=r"(r1), "=r"(r2), "=r"(r3) : "r"(addr))

#define MMA16816(d, a0, a1, a2, a3, b0, b1) \
    asm volatile("mma.sync.aligned.m16n8k16.row.col.f32.f16.f16.f32 " \
                 "{%0,%1,%2,%3}, {%4,%5,%6,%7}, {%8,%9}, {%0,%1,%2,%3};" \
                 : "+f"((d)[0]), "+f"((d)[1]), "+f"((d)[2]), "+f"((d)[3]) \
                 : "r"(a0), "r"(a1), "r"(a2), "r"(a3), "r"(b0), "r"(b1))

// ---------------------------------------------------------------------------
// prep_w: one block per class; phys K=1024 layout + bias
// ---------------------------------------------------------------------------
__global__ void prep_w_kernel(const float* __restrict__ centers,
                              const float* __restrict__ Droot) {
    int k = blockIdx.x;
    int d = threadIdx.x;
    int idx = k * NDIM + d;

    float D    = fabsf(Droot[idx]) + 1e-4f;
    float dinv = 1.0f / D;
    float c    = centers[idx];

    float w1 = -0.5f * dinv;
    float w2 = c * dinv;
    __half w1h = __float2half_rn(w1);
    __half w1l = __float2half_rn(w1 - __half2float(w1h));
    __half w2h = __float2half_rn(w2);
    __half w2l = __float2half_rn(w2 - __half2float(w2h));

    __half* row = g_w + (size_t)k * 1024;
    row[d]       = w1h;
    row[256 + d] = w2h;
    row[512 + d] = w1l;
    row[768 + d] = w2l;

    float p = c * c * dinv + logf(D);
    __shared__ float red[8];
    #pragma unroll
    for (int o = 16; o; o >>= 1) p += __shfl_xor_sync(0xFFFFFFFFu, p, o);
    if ((threadIdx.x & 31) == 0) red[threadIdx.x >> 5] = p;
    __syncthreads();
    if (threadIdx.x < 8) {
        float v = red[threadIdx.x];
        #pragma unroll
        for (int o = 4; o; o >>= 1) v += __shfl_xor_sync(0xFFu, v, o);
        if (threadIdx.x == 0) g_bias[k] = -0.5f * v;
    }
}

// ---------------------------------------------------------------------------
// issue_pair: cp.async B stage p (hi) + stage p+8 (lo) into pair buffer p&1.
// 16 cp.async of 16B per thread, one commit group (64KB total).
// ---------------------------------------------------------------------------
__device__ __forceinline__ void issue_pair(unsigned char* sm, int t, int p) {
    unsigned base = smem_u32(sm + (p & 1) * PAIR_BYTES);
    const int j  = t & 7;
    const int k0 = t >> 3;
    #pragma unroll
    for (int i = 0; i < 8; i++) {
        int k = k0 + 32 * i;
        unsigned sw  = (unsigned)(j ^ (k & 7)) << 4;
        unsigned dsth = base + k * 128 + sw;
        const __half* srch = g_w + (size_t)k * 1024 + p * 64 + j * 8;
        asm volatile("cp.async.cg.shared.global [%0], [%1], 16;" :: "r"(dsth), "l"(srch));
        unsigned dstl = dsth + 32768;
        const __half* srcl = srch + 512;   // stage p+8
        asm volatile("cp.async.cg.shared.global [%0], [%1], 16;" :: "r"(dstl), "l"(srcl));
    }
    asm volatile("cp.async.commit_group;");
}

// ---------------------------------------------------------------------------
// Fused kernel: CTA = 32 rows x 256 classes, 256 threads (8 n-warps of 32 cols)
// logit = sum phi_hi*w_hi + phi_lo*w_hi + phi_hi*w_lo + bias; softmax fused.
// ---------------------------------------------------------------------------
__global__ __launch_bounds__(256, 1) void gmm_fused_kernel(
        const float* __restrict__ x, float* __restrict__ out) {
    extern __shared__ __align__(128) unsigned char sm[];
    const int t    = threadIdx.x;
    const int lane = t & 31;
    const int wid  = t >> 5;
    const int b0   = blockIdx.x * MT;

    // ---- prologue: start pair 0, convert x -> phi in smem A ----
    issue_pair(sm, t, 0);

    {
        // thread: row r = t>>3, dims [seg*32, seg*32+32)
        const int r   = t >> 3;
        const int seg = t & 7;
        const float* xr = x + (size_t)(b0 + r) * NDIM + seg * 32;
        unsigned arow = smem_u32(sm + A_OFF) + r * 2048;
        const unsigned rs = (unsigned)(r & 7);
        #pragma unroll
        for (int c = 0; c < 4; c++) {
            float4 xa = *(const float4*)(xr + c * 8);
            float4 xb = *(const float4*)(xr + c * 8 + 4);
            float v[8] = {xa.x, xa.y, xa.z, xa.w, xb.x, xb.y, xb.z, xb.w};
            __half x2h[8], x2l[8], xh[8], xl[8];
            #pragma unroll
            for (int e = 0; e < 8; e++) {
                float a = v[e] * v[e];
                x2h[e] = __float2half_rn(a);
                x2l[e] = __float2half_rn(a - __half2float(x2h[e]));
                xh[e]  = __float2half_rn(v[e]);
                xl[e]  = __float2half_rn(v[e] - __half2float(xh[e]));
            }
            const int db = seg * 32 + c * 8;
            const __half* regs[4] = {x2h, xh, x2l, xl};
            #pragma unroll
            for (int Rg = 0; Rg < 4; Rg++) {
                // phi phys: [x2_hi | x_hi | x2_lo | x_lo] (stages 0-3,4-7,8-11,12-15)
                int p0 = Rg * 256 + db;
                int ks = p0 >> 6;
                unsigned j = (unsigned)((p0 >> 3) & 7);
                unsigned addr = arow + ks * 128 + ((j ^ rs) << 4);
                const __half* h = regs[Rg];
                unsigned w0 = pack2(h[0], h[1]);
                unsigned w1 = pack2(h[2], h[3]);
                unsigned w2 = pack2(h[4], h[5]);
                unsigned w3 = pack2(h[6], h[7]);
                asm volatile("st.shared.v4.b32 [%0], {%1,%2,%3,%4};"
                             :: "r"(addr), "r"(w0), "r"(w1), "r"(w2), "r"(w3));
            }
        }
    }

    // ---- stage-invariant ldmatrix offsets ----
    unsigned offa[2][4], offb[2][4];
    {
        const int arow = lane & 15;
        const int akh  = lane >> 4;
        const int brow = wid * 32 + (lane & 7) + ((lane >> 4) & 1) * 8;
        const int bkh  = (lane >> 3) & 1;
        #pragma unroll
        for (int ks = 0; ks < 4; ks++) {
            #pragma unroll
            for (int mt = 0; mt < 2; mt++) {
                int r = arow + mt * 16;
                offa[mt][ks] = (unsigned)(r * 2048) +
                               ((unsigned)((ks * 2 + akh) ^ (r & 7)) << 4);
            }
            #pragma unroll
            for (int np = 0; np < 2; np++) {
                int r = brow + np * 16;
                offb[np][ks] = (unsigned)(r * 128) +
                               ((unsigned)((ks * 2 + bkh) ^ (r & 7)) << 4);
            }
        }
    }

    float d[2][4][4];
    #pragma unroll
    for (int mt = 0; mt < 2; mt++)
        #pragma unroll
        for (int nt = 0; nt < 4; nt++)
            #pragma unroll
            for (int e = 0; e < 4; e++) d[mt][nt][e] = 0.0f;

    const unsigned abase0 = smem_u32(sm + A_OFF);

    // ---- mainloop: 8 iterations, 3 products per fragment set ----
    for (int p = 0; p < NP; p++) {
        asm volatile("cp.async.wait_group 0;");   // pair p resident
        __syncthreads();                          // visible to all; pair p-1 slot free
        if (p + 1 < NP) issue_pair(sm, t, p + 1); // refill freed slot, overlap compute

        unsigned bh = smem_u32(sm + (p & 1) * PAIR_BYTES);
        unsigned bl = bh + 32768;
        unsigned ah = abase0 + (unsigned)(p * 128);        // A_hi stage p
        unsigned al = ah + 1024;                           // A_lo stage p+8

        #pragma unroll
        for (int ks = 0; ks < 4; ks++) {
            unsigned Ah[2][4], Al[2][4], Bh[2][4], Bl[2][4];
            #pragma unroll
            for (int mt = 0; mt < 2; mt++) {
                LDSM_X4(Ah[mt][0], Ah[mt][1], Ah[mt][2], Ah[mt][3], ah + offa[mt][ks]);
                LDSM_X4(Al[mt][0], Al[mt][1], Al[mt][2], Al[mt][3], al + offa[mt][ks]);
            }
            #pragma unroll
            for (int np = 0; np < 2; np++) {
                LDSM_X4(Bh[np][0], Bh[np][1], Bh[np][2], Bh[np][3], bh + offb[np][ks]);
                LDSM_X4(Bl[np][0], Bl[np][1], Bl[np][2], Bl[np][3], bl + offb[np][ks]);
            }
            #pragma unroll
            for (int mt = 0; mt < 2; mt++)
                #pragma unroll
                for (int nt = 0; nt < 4; nt++) {
                    int np = nt >> 1, o = (nt & 1) * 2;
                    MMA16816(d[mt][nt], Ah[mt][0], Ah[mt][1], Ah[mt][2], Ah[mt][3],
                             Bh[np][o], Bh[np][o + 1]);
                }
            #pragma unroll
            for (int mt = 0; mt < 2; mt++)
                #pragma unroll
                for (int nt = 0; nt < 4; nt++) {
                    int np = nt >> 1, o = (nt & 1) * 2;
                    MMA16816(d[mt][nt], Al[mt][0], Al[mt][1], Al[mt][2], Al[mt][3],
                             Bh[np][o], Bh[np][o + 1]);
                }
            #pragma unroll
            for (int mt = 0; mt < 2; mt++)
                #pragma unroll
                for (int nt = 0; nt < 4; nt++) {
                    int np = nt >> 1, o = (nt & 1) * 2;
                    MMA16816(d[mt][nt], Ah[mt][0], Ah[mt][1], Ah[mt][2], Ah[mt][3],
                             Bl[np][o], Bl[np][o + 1]);
                }
        }
    }

    // ---- epilogue: logits (+bias) into smem (reuse pair buffers), softmax ----
    float* ls = (float*)sm;   // 32 rows x 256 cols f32 = 32KB
    __syncthreads();
    #pragma unroll
    for (int mt = 0; mt < 2; mt++) {
        int row = mt * 16 + (lane >> 2);
        #pragma unroll
        for (int nt = 0; nt < 4; nt++) {
            int col = wid * 32 + nt * 8 + (lane & 3) * 2;
            float2 bv = *(const float2*)(g_bias + col);
            float2 v0 = {d[mt][nt][0] + bv.x, d[mt][nt][1] + bv.y};
            float2 v1 = {d[mt][nt][2] + bv.x, d[mt][nt][3] + bv.y};
            *(float2*)(ls + row * NCLS + col)       = v0;
            *(float2*)(ls + (row + 8) * NCLS + col) = v1;
        }
    }
    __syncthreads();

    #pragma unroll
    for (int rr = 0; rr < 4; rr++) {
        int r = wid * 4 + rr;
        const float4* lrow = (const float4*)(ls + r * NCLS);
        float4 a = lrow[lane * 2];
        float4 b = lrow[lane * 2 + 1];

        float mx = fmaxf(fmaxf(fmaxf(a.x, a.y), fmaxf(a.z, a.w)),
                         fmaxf(fmaxf(b.x, b.y), fmaxf(b.z, b.w)));
        #pragma unroll
        for (int o = 16; o; o >>= 1) mx = fmaxf(mx, __shfl_xor_sync(0xFFFFFFFFu, mx, o));

        float4 ea, eb;
        ea.x = __expf(a.x - mx); ea.y = __expf(a.y - mx);
        ea.z = __expf(a.z - mx); ea.w = __expf(a.w - mx);
        eb.x = __expf(b.x - mx); eb.y = __expf(b.y - mx);
        eb.z = __expf(b.z - mx); eb.w = __expf(b.w - mx);

        float sum = (ea.x + ea.y) + (ea.z + ea.w) + (eb.x + eb.y) + (eb.z + eb.w);
        #pragma unroll
        for (int o = 16; o; o >>= 1) sum += __shfl_xor_sync(0xFFFFFFFFu, sum, o);

        float inv = 1.0f / sum;
        ea.x *= inv; ea.y *= inv; ea.z *= inv; ea.w *= inv;
        eb.x *= inv; eb.y *= inv; eb.z *= inv; eb.w *= inv;

        float4* orow = (float4*)(out + (size_t)(b0 + r) * NCLS);
        orow[lane * 2]     = ea;
        orow[lane * 2 + 1] = eb;
    }
}

// ---------------------------------------------------------------------------
extern "C" void kernel_launch(void* const* d_in, const int* in_sizes, int n_in,
                              void* d_out, int out_size) {
    const float* x       = (const float*)d_in[0];
    const float* centers = (const float*)d_in[1];
    const float* Droot   = (const float*)d_in[2];
    float*       out     = (float*)d_out;

    cudaFuncSetAttribute(gmm_fused_kernel,
                         cudaFuncAttributeMaxDynamicSharedMemorySize, SMEM_TOTAL);

    prep_w_kernel<<<NCLS, NDIM>>>(centers, Droot);
    gmm_fused_kernel<<<BATCH / MT, 256, SMEM_TOTAL>>>(x, out);
}

// round 12
// speedup vs baseline: 1.2953x; 1.0746x over previous
#include <cuda_runtime.h>
#include <cuda_fp16.h>
#include <cstdint>
#include <math.h>

#define BATCH 4096
#define NCLS  256
#define NDIM  256

#define MT 32                    // batch rows per CTA
#define NTHR 512                 // 16 warps
#define NP 8                     // hi/lo pair iterations
#define PAIR_BYTES 65536         // B_hi stage (32KB) + B_lo stage (32KB)
#define A_OFF   (2 * PAIR_BYTES)            // 131072
#define A_BYTES (MT * 1024 * 2)             // 64KB (phys K=1024 per row)
#define SMEM_TOTAL (A_OFF + A_BYTES)        // 192KB

// W phys layout per class row (K=1024): [w1_hi|w2_hi|w1_lo|w2_lo] (256 each)
// -> 16 chunk-stages of 64 halves; stage p = hi dims, stage p+8 = lo dims
__device__ __align__(16) __half g_w[NCLS * 1024];      // 512KB
__device__ __align__(16) float  g_bias[NCLS];

// ---------------------------------------------------------------------------
__device__ __forceinline__ unsigned smem_u32(const void* p) {
    return (unsigned)__cvta_generic_to_shared(p);
}
__device__ __forceinline__ unsigned pack2(__half lo, __half hi) {
    return (unsigned)__half_as_ushort(lo) | ((unsigned)__half_as_ushort(hi) << 16);
}

#define LDSM_X4(r0, r1, r2, r3, addr) \
    asm volatile("ldmatrix.sync.aligned.m8n8.x4.shared.b16 {%0,%1,%2,%3}, [%4];" \
                 : "=r"(r0), "=r"(r1), "=r"(r2), "=r"(r3) : "r"(addr))

#define MMA16816(d, a0, a1, a2, a3, b0, b1) \
    asm volatile("mma.sync.aligned.m16n8k16.row.col.f32.f16.f16.f32 " \
                 "{%0,%1,%2,%3}, {%4,%5,%6,%7}, {%8,%9}, {%0,%1,%2,%3};" \
                 : "+f"((d)[0]), "+f"((d)[1]), "+f"((d)[2]), "+f"((d)[3]) \
                 : "r"(a0), "r"(a1), "r"(a2), "r"(a3), "r"(b0), "r"(b1))

// ---------------------------------------------------------------------------
// prep_w: one block per class; phys K=1024 layout + bias
// ---------------------------------------------------------------------------
__global__ void prep_w_kernel(const float* __restrict__ centers,
                              const float* __restrict__ Droot) {
    int k = blockIdx.x;
    int d = threadIdx.x;
    int idx = k * NDIM + d;

    float D    = fabsf(Droot[idx]) + 1e-4f;
    float dinv = 1.0f / D;
    float c    = centers[idx];

    float w1 = -0.5f * dinv;
    float w2 = c * dinv;
    __half w1h = __float2half_rn(w1);
    __half w1l = __float2half_rn(w1 - __half2float(w1h));
    __half w2h = __float2half_rn(w2);
    __half w2l = __float2half_rn(w2 - __half2float(w2h));

    __half* row = g_w + (size_t)k * 1024;
    row[d]       = w1h;
    row[256 + d] = w2h;
    row[512 + d] = w1l;
    row[768 + d] = w2l;

    float p = c * c * dinv + logf(D);
    __shared__ float red[8];
    #pragma unroll
    for (int o = 16; o; o >>= 1) p += __shfl_xor_sync(0xFFFFFFFFu, p, o);
    if ((threadIdx.x & 31) == 0) red[threadIdx.x >> 5] = p;
    __syncthreads();
    if (threadIdx.x < 8) {
        float v = red[threadIdx.x];
        #pragma unroll
        for (int o = 4; o; o >>= 1) v += __shfl_xor_sync(0xFFu, v, o);
        if (threadIdx.x == 0) g_bias[k] = -0.5f * v;
    }
}

// ---------------------------------------------------------------------------
// issue_pair: cp.async B stage p (hi) + stage p+8 (lo) into pair buffer p&1.
// 512 threads x 8 cp.async of 16B = 64KB, one commit group.
// ---------------------------------------------------------------------------
__device__ __forceinline__ void issue_pair(unsigned char* sm, int t, int p) {
    unsigned base = smem_u32(sm + (p & 1) * PAIR_BYTES);
    const int j  = t & 7;
    const int k0 = t >> 3;     // 0..63
    #pragma unroll
    for (int i = 0; i < 4; i++) {
        int k = k0 + 64 * i;
        unsigned sw   = (unsigned)(j ^ (k & 7)) << 4;
        unsigned dsth = base + k * 128 + sw;
        const __half* srch = g_w + (size_t)k * 1024 + p * 64 + j * 8;
        asm volatile("cp.async.cg.shared.global [%0], [%1], 16;" :: "r"(dsth), "l"(srch));
        unsigned dstl = dsth + 32768;
        const __half* srcl = srch + 512;   // stage p+8 (lo)
        asm volatile("cp.async.cg.shared.global [%0], [%1], 16;" :: "r"(dstl), "l"(srcl));
    }
    asm volatile("cp.async.commit_group;");
}

// ---------------------------------------------------------------------------
// Fused kernel: CTA = 32 rows x 256 classes, 512 threads (16 n-warps x 16 cols)
// logit = sum phi_hi*w_hi + phi_lo*w_hi + phi_hi*w_lo + bias; softmax fused.
// ---------------------------------------------------------------------------
__global__ __launch_bounds__(NTHR, 1) void gmm_fused_kernel(
        const float* __restrict__ x, float* __restrict__ out) {
    extern __shared__ __align__(128) unsigned char sm[];
    const int t    = threadIdx.x;
    const int lane = t & 31;
    const int wid  = t >> 5;                // 0..15
    const int b0   = blockIdx.x * MT;

    // ---- prologue: start pair 0, convert x -> phi in smem A ----
    issue_pair(sm, t, 0);

    {
        // thread: row r = t>>4, dims [seg*16, seg*16+16)
        const int r   = t >> 4;
        const int seg = t & 15;
        const float* xr = x + (size_t)(b0 + r) * NDIM + seg * 16;
        unsigned arow = smem_u32(sm + A_OFF) + r * 2048;
        const unsigned rs = (unsigned)(r & 7);
        #pragma unroll
        for (int c = 0; c < 2; c++) {
            float4 xa = *(const float4*)(xr + c * 8);
            float4 xb = *(const float4*)(xr + c * 8 + 4);
            float v[8] = {xa.x, xa.y, xa.z, xa.w, xb.x, xb.y, xb.z, xb.w};
            __half x2h[8], x2l[8], xh[8], xl[8];
            #pragma unroll
            for (int e = 0; e < 8; e++) {
                float a = v[e] * v[e];
                x2h[e] = __float2half_rn(a);
                x2l[e] = __float2half_rn(a - __half2float(x2h[e]));
                xh[e]  = __float2half_rn(v[e]);
                xl[e]  = __float2half_rn(v[e] - __half2float(xh[e]));
            }
            const int db = seg * 16 + c * 8;
            const __half* regs[4] = {x2h, xh, x2l, xl};
            #pragma unroll
            for (int Rg = 0; Rg < 4; Rg++) {
                // phi phys: [x2_hi | x_hi | x2_lo | x_lo]
                int p0 = Rg * 256 + db;
                int ks = p0 >> 6;
                unsigned j = (unsigned)((p0 >> 3) & 7);
                unsigned addr = arow + ks * 128 + ((j ^ rs) << 4);
                const __half* h = regs[Rg];
                unsigned w0 = pack2(h[0], h[1]);
                unsigned w1 = pack2(h[2], h[3]);
                unsigned w2 = pack2(h[4], h[5]);
                unsigned w3 = pack2(h[6], h[7]);
                asm volatile("st.shared.v4.b32 [%0], {%1,%2,%3,%4};"
                             :: "r"(addr), "r"(w0), "r"(w1), "r"(w2), "r"(w3));
            }
        }
    }

    // ---- stage-invariant ldmatrix offsets ----
    // A: rows = lane&15 (+ mt*16), k-half = lane>>4
    // B: 16 classes per warp; lanes 0-7: cls wid*16+(lane&7) kh0, 8-15: kh1,
    //    16-23: cls +8 kh0, 24-31: cls +8 kh1  -> x4 gives 16 cls x k16
    unsigned offa[2][4], offb[4];
    {
        const int arow = lane & 15;
        const int akh  = lane >> 4;
        const int brow = wid * 16 + (lane & 7) + ((lane >> 4) & 1) * 8;
        const int bkh  = (lane >> 3) & 1;
        #pragma unroll
        for (int ks = 0; ks < 4; ks++) {
            #pragma unroll
            for (int mt = 0; mt < 2; mt++) {
                int r = arow + mt * 16;
                offa[mt][ks] = (unsigned)(r * 2048) +
                               ((unsigned)((ks * 2 + akh) ^ (r & 7)) << 4);
            }
            offb[ks] = (unsigned)(brow * 128) +
                       ((unsigned)((ks * 2 + bkh) ^ (brow & 7)) << 4);
        }
    }

    float d[2][2][4];
    #pragma unroll
    for (int mt = 0; mt < 2; mt++)
        #pragma unroll
        for (int nt = 0; nt < 2; nt++)
            #pragma unroll
            for (int e = 0; e < 4; e++) d[mt][nt][e] = 0.0f;

    const unsigned abase0 = smem_u32(sm + A_OFF);

    // ---- mainloop: 8 iterations, 3 products per fragment set ----
    for (int p = 0; p < NP; p++) {
        asm volatile("cp.async.wait_group 0;");   // pair p resident
        __syncthreads();                          // visible; pair p-1 slot free
        if (p + 1 < NP) issue_pair(sm, t, p + 1); // refill, overlap compute

        unsigned bh = smem_u32(sm + (p & 1) * PAIR_BYTES);
        unsigned bl = bh + 32768;
        unsigned ah = abase0 + (unsigned)(p * 128);    // A_hi stage p
        unsigned al = ah + 1024;                       // A_lo stage p+8

        #pragma unroll
        for (int ks = 0; ks < 4; ks++) {
            unsigned Ah[2][4], Al[2][4], Bh[4], Bl[4];
            #pragma unroll
            for (int mt = 0; mt < 2; mt++) {
                LDSM_X4(Ah[mt][0], Ah[mt][1], Ah[mt][2], Ah[mt][3], ah + offa[mt][ks]);
                LDSM_X4(Al[mt][0], Al[mt][1], Al[mt][2], Al[mt][3], al + offa[mt][ks]);
            }
            LDSM_X4(Bh[0], Bh[1], Bh[2], Bh[3], bh + offb[ks]);
            LDSM_X4(Bl[0], Bl[1], Bl[2], Bl[3], bl + offb[ks]);

            #pragma unroll
            for (int mt = 0; mt < 2; mt++)
                #pragma unroll
                for (int nt = 0; nt < 2; nt++)
                    MMA16816(d[mt][nt], Ah[mt][0], Ah[mt][1], Ah[mt][2], Ah[mt][3],
                             Bh[nt * 2], Bh[nt * 2 + 1]);
            #pragma unroll
            for (int mt = 0; mt < 2; mt++)
                #pragma unroll
                for (int nt = 0; nt < 2; nt++)
                    MMA16816(d[mt][nt], Al[mt][0], Al[mt][1], Al[mt][2], Al[mt][3],
                             Bh[nt * 2], Bh[nt * 2 + 1]);
            #pragma unroll
            for (int mt = 0; mt < 2; mt++)
                #pragma unroll
                for (int nt = 0; nt < 2; nt++)
                    MMA16816(d[mt][nt], Ah[mt][0], Ah[mt][1], Ah[mt][2], Ah[mt][3],
                             Bl[nt * 2], Bl[nt * 2 + 1]);
        }
    }

    // ---- epilogue: logits (+bias) into smem (reuse pair buffers), softmax ----
    float* ls = (float*)sm;   // 32 rows x 256 cols f32 = 32KB
    __syncthreads();
    #pragma unroll
    for (int mt = 0; mt < 2; mt++) {
        int row = mt * 16 + (lane >> 2);
        #pragma unroll
        for (int nt = 0; nt < 2; nt++) {
            int col = wid * 16 + nt * 8 + (lane & 3) * 2;
            float2 bv = *(const float2*)(g_bias + col);
            float2 v0 = {d[mt][nt][0] + bv.x, d[mt][nt][1] + bv.y};
            float2 v1 = {d[mt][nt][2] + bv.x, d[mt][nt][3] + bv.y};
            *(float2*)(ls + row * NCLS + col)       = v0;
            *(float2*)(ls + (row + 8) * NCLS + col) = v1;
        }
    }
    __syncthreads();

    // warp handles rows wid*2, wid*2+1
    #pragma unroll
    for (int rr = 0; rr < 2; rr++) {
        int r = wid * 2 + rr;
        const float4* lrow = (const float4*)(ls + r * NCLS);
        float4 a = lrow[lane * 2];
        float4 b = lrow[lane * 2 + 1];

        float mx = fmaxf(fmaxf(fmaxf(a.x, a.y), fmaxf(a.z, a.w)),
                         fmaxf(fmaxf(b.x, b.y), fmaxf(b.z, b.w)));
        #pragma unroll
        for (int o = 16; o; o >>= 1) mx = fmaxf(mx, __shfl_xor_sync(0xFFFFFFFFu, mx, o));

        float4 ea, eb;
        ea.x = __expf(a.x - mx); ea.y = __expf(a.y - mx);
        ea.z = __expf(a.z - mx); ea.w = __expf(a.w - mx);
        eb.x = __expf(b.x - mx); eb.y = __expf(b.y - mx);
        eb.z = __expf(b.z - mx); eb.w = __expf(b.w - mx);

        float sum = (ea.x + ea.y) + (ea.z + ea.w) + (eb.x + eb.y) + (eb.z + eb.w);
        #pragma unroll
        for (int o = 16; o; o >>= 1) sum += __shfl_xor_sync(0xFFFFFFFFu, sum, o);

        float inv = 1.0f / sum;
        ea.x *= inv; ea.y *= inv; ea.z *= inv; ea.w *= inv;
        eb.x *= inv; eb.y *= inv; eb.z *= inv; eb.w *= inv;

        float4* orow = (float4*)(out + (size_t)(b0 + r) * NCLS);
        orow[lane * 2]     = ea;
        orow[lane * 2 + 1] = eb;
    }
}

// ---------------------------------------------------------------------------
extern "C" void kernel_launch(void* const* d_in, const int* in_sizes, int n_in,
                              void* d_out, int out_size) {
    const float* x       = (const float*)d_in[0];
    const float* centers = (const float*)d_in[1];
    const float* Droot   = (const float*)d_in[2];
    float*       out     = (float*)d_out;

    cudaFuncSetAttribute(gmm_fused_kernel,
                         cudaFuncAttributeMaxDynamicSharedMemorySize, SMEM_TOTAL);

    prep_w_kernel<<<NCLS, NDIM>>>(centers, Droot);
    gmm_fused_kernel<<<BATCH / MT, NTHR, SMEM_TOTAL>>>(x, out);
}

// round 13
// speedup vs baseline: 1.3153x; 1.0155x over previous
#include <cuda_runtime.h>
#include <cuda_fp16.h>
#include <cstdint>
#include <math.h>

#define BATCH 4096
#define NCLS  256
#define NDIM  256

#define MT 32                    // batch rows per CTA
#define NTHR 512                 // 16 warps
#define NP 8                     // hi/lo pair iterations
#define PAIR_BYTES 65536         // B_hi stage (32KB) + B_lo stage (32KB)
#define A_OFF   (2 * PAIR_BYTES)            // 131072
#define A_BYTES (MT * 1024 * 2)             // 64KB (phys K=1024 per row)
#define SMEM_TOTAL (A_OFF + A_BYTES)        // 192KB

// W phys layout per class row (K=1024): [w1_hi|w2_hi|w1_lo|w2_lo] (256 each)
// -> 16 chunk-stages of 64 halves; stage p = hi dims, stage p+8 = lo dims
__device__ __align__(16) __half g_w[NCLS * 1024];      // 512KB
__device__ __align__(16) float  g_bias[NCLS];

// ---------------------------------------------------------------------------
__device__ __forceinline__ unsigned smem_u32(const void* p) {
    return (unsigned)__cvta_generic_to_shared(p);
}
__device__ __forceinline__ unsigned pack2(__half lo, __half hi) {
    return (unsigned)__half_as_ushort(lo) | ((unsigned)__half_as_ushort(hi) << 16);
}

#define LDSM_X4(r0, r1, r2, r3, addr) \
    asm volatile("ldmatrix.sync.aligned.m8n8.x4.shared.b16 {%0,%1,%2,%3}, [%4];" \
                 : "=r"(r0), "=r"(r1), "=r"(r2), "=r"(r3) : "r"(addr))

#define MMA16816(d, a0, a1, a2, a3, b0, b1) \
    asm volatile("mma.sync.aligned.m16n8k16.row.col.f32.f16.f16.f32 " \
                 "{%0,%1,%2,%3}, {%4,%5,%6,%7}, {%8,%9}, {%0,%1,%2,%3};" \
                 : "+f"((d)[0]), "+f"((d)[1]), "+f"((d)[2]), "+f"((d)[3]) \
                 : "r"(a0), "r"(a1), "r"(a2), "r"(a3), "r"(b0), "r"(b1))

// ---------------------------------------------------------------------------
// prep_w: one block per class; phys K=1024 layout + bias
// ---------------------------------------------------------------------------
__global__ void prep_w_kernel(const float* __restrict__ centers,
                              const float* __restrict__ Droot) {
    int k = blockIdx.x;
    int d = threadIdx.x;
    int idx = k * NDIM + d;

    float D    = fabsf(Droot[idx]) + 1e-4f;
    float dinv = 1.0f / D;
    float c    = centers[idx];

    float w1 = -0.5f * dinv;
    float w2 = c * dinv;
    __half w1h = __float2half_rn(w1);
    __half w1l = __float2half_rn(w1 - __half2float(w1h));
    __half w2h = __float2half_rn(w2);
    __half w2l = __float2half_rn(w2 - __half2float(w2h));

    __half* row = g_w + (size_t)k * 1024;
    row[d]       = w1h;
    row[256 + d] = w2h;
    row[512 + d] = w1l;
    row[768 + d] = w2l;

    float p = c * c * dinv + logf(D);
    __shared__ float red[8];
    #pragma unroll
    for (int o = 16; o; o >>= 1) p += __shfl_xor_sync(0xFFFFFFFFu, p, o);
    if ((threadIdx.x & 31) == 0) red[threadIdx.x >> 5] = p;
    __syncthreads();
    if (threadIdx.x < 8) {
        float v = red[threadIdx.x];
        #pragma unroll
        for (int o = 4; o; o >>= 1) v += __shfl_xor_sync(0xFFu, v, o);
        if (threadIdx.x == 0) g_bias[k] = -0.5f * v;
    }
}

// ---------------------------------------------------------------------------
// issue_pair: cp.async B stage p (hi) + stage p+8 (lo) into pair buffer p&1.
// 512 threads x 8 cp.async of 16B = 64KB, one commit group.
// ---------------------------------------------------------------------------
__device__ __forceinline__ void issue_pair(unsigned char* sm, int t, int p) {
    unsigned base = smem_u32(sm + (p & 1) * PAIR_BYTES);
    const int j  = t & 7;
    const int k0 = t >> 3;     // 0..63
    #pragma unroll
    for (int i = 0; i < 4; i++) {
        int k = k0 + 64 * i;
        unsigned sw   = (unsigned)(j ^ (k & 7)) << 4;
        unsigned dsth = base + k * 128 + sw;
        const __half* srch = g_w + (size_t)k * 1024 + p * 64 + j * 8;
        asm volatile("cp.async.cg.shared.global [%0], [%1], 16;" :: "r"(dsth), "l"(srch));
        unsigned dstl = dsth + 32768;
        const __half* srcl = srch + 512;   // stage p+8 (lo)
        asm volatile("cp.async.cg.shared.global [%0], [%1], 16;" :: "r"(dstl), "l"(srcl));
    }
    asm volatile("cp.async.commit_group;");
}

// ---------------------------------------------------------------------------
// Fused kernel: CTA = 32 rows x 256 classes, 512 threads (16 n-warps x 16 cols)
// logit = sum phi_hi*w_hi + phi_lo*w_hi + phi_hi*w_lo + bias; softmax fused.
// Register-level 2-stage fragment pipeline in the ks loop.
// ---------------------------------------------------------------------------
__global__ __launch_bounds__(NTHR, 1) void gmm_fused_kernel(
        const float* __restrict__ x, float* __restrict__ out) {
    extern __shared__ __align__(128) unsigned char sm[];
    const int t    = threadIdx.x;
    const int lane = t & 31;
    const int wid  = t >> 5;                // 0..15
    const int b0   = blockIdx.x * MT;

    // ---- prologue: start pair 0, convert x -> phi in smem A ----
    issue_pair(sm, t, 0);

    {
        // thread: row r = t>>4, dims [seg*16, seg*16+16)
        const int r   = t >> 4;
        const int seg = t & 15;
        const float* xr = x + (size_t)(b0 + r) * NDIM + seg * 16;
        unsigned arow = smem_u32(sm + A_OFF) + r * 2048;
        const unsigned rs = (unsigned)(r & 7);
        #pragma unroll
        for (int c = 0; c < 2; c++) {
            float4 xa = *(const float4*)(xr + c * 8);
            float4 xb = *(const float4*)(xr + c * 8 + 4);
            float v[8] = {xa.x, xa.y, xa.z, xa.w, xb.x, xb.y, xb.z, xb.w};
            __half x2h[8], x2l[8], xh[8], xl[8];
            #pragma unroll
            for (int e = 0; e < 8; e++) {
                float a = v[e] * v[e];
                x2h[e] = __float2half_rn(a);
                x2l[e] = __float2half_rn(a - __half2float(x2h[e]));
                xh[e]  = __float2half_rn(v[e]);
                xl[e]  = __float2half_rn(v[e] - __half2float(xh[e]));
            }
            const int db = seg * 16 + c * 8;
            const __half* regs[4] = {x2h, xh, x2l, xl};
            #pragma unroll
            for (int Rg = 0; Rg < 4; Rg++) {
                // phi phys: [x2_hi | x_hi | x2_lo | x_lo]
                int p0 = Rg * 256 + db;
                int ks = p0 >> 6;
                unsigned j = (unsigned)((p0 >> 3) & 7);
                unsigned addr = arow + ks * 128 + ((j ^ rs) << 4);
                const __half* h = regs[Rg];
                unsigned w0 = pack2(h[0], h[1]);
                unsigned w1 = pack2(h[2], h[3]);
                unsigned w2 = pack2(h[4], h[5]);
                unsigned w3 = pack2(h[6], h[7]);
                asm volatile("st.shared.v4.b32 [%0], {%1,%2,%3,%4};"
                             :: "r"(addr), "r"(w0), "r"(w1), "r"(w2), "r"(w3));
            }
        }
    }

    // ---- stage-invariant ldmatrix offsets ----
    unsigned offa[2][4], offb[4];
    {
        const int arow = lane & 15;
        const int akh  = lane >> 4;
        const int brow = wid * 16 + (lane & 7) + ((lane >> 4) & 1) * 8;
        const int bkh  = (lane >> 3) & 1;
        #pragma unroll
        for (int ks = 0; ks < 4; ks++) {
            #pragma unroll
            for (int mt = 0; mt < 2; mt++) {
                int r = arow + mt * 16;
                offa[mt][ks] = (unsigned)(r * 2048) +
                               ((unsigned)((ks * 2 + akh) ^ (r & 7)) << 4);
            }
            offb[ks] = (unsigned)(brow * 128) +
                       ((unsigned)((ks * 2 + bkh) ^ (brow & 7)) << 4);
        }
    }

    float d[2][2][4];
    #pragma unroll
    for (int mt = 0; mt < 2; mt++)
        #pragma unroll
        for (int nt = 0; nt < 2; nt++)
            #pragma unroll
            for (int e = 0; e < 4; e++) d[mt][nt][e] = 0.0f;

    const unsigned abase0 = smem_u32(sm + A_OFF);

    // ---- mainloop: 8 iterations; 2-stage fragment pipeline over ks ----
    for (int p = 0; p < NP; p++) {
        asm volatile("cp.async.wait_group 0;");   // pair p resident
        __syncthreads();                          // visible; pair p-1 slot free
        if (p + 1 < NP) issue_pair(sm, t, p + 1); // refill, overlap compute

        unsigned bh = smem_u32(sm + (p & 1) * PAIR_BYTES);
        unsigned bl = bh + 32768;
        unsigned ah = abase0 + (unsigned)(p * 128);    // A_hi stage p
        unsigned al = ah + 1024;                       // A_lo stage p+8

        // fragment double buffers
        unsigned Ah[2][2][4], Al[2][2][4], Bh[2][4], Bl[2][4];

        // preload ks=0 into buffer 0
        #pragma unroll
        for (int mt = 0; mt < 2; mt++) {
            LDSM_X4(Ah[0][mt][0], Ah[0][mt][1], Ah[0][mt][2], Ah[0][mt][3],
                    ah + offa[mt][0]);
            LDSM_X4(Al[0][mt][0], Al[0][mt][1], Al[0][mt][2], Al[0][mt][3],
                    al + offa[mt][0]);
        }
        LDSM_X4(Bh[0][0], Bh[0][1], Bh[0][2], Bh[0][3], bh + offb[0]);
        LDSM_X4(Bl[0][0], Bl[0][1], Bl[0][2], Bl[0][3], bl + offb[0]);

        #pragma unroll
        for (int ks = 0; ks < 4; ks++) {
            const int cur = ks & 1;
            const int nxt = cur ^ 1;
            if (ks < 3) {   // prefetch ks+1 fragments; overlaps MMAs below
                #pragma unroll
                for (int mt = 0; mt < 2; mt++) {
                    LDSM_X4(Ah[nxt][mt][0], Ah[nxt][mt][1], Ah[nxt][mt][2],
                            Ah[nxt][mt][3], ah + offa[mt][ks + 1]);
                    LDSM_X4(Al[nxt][mt][0], Al[nxt][mt][1], Al[nxt][mt][2],
                            Al[nxt][mt][3], al + offa[mt][ks + 1]);
                }
                LDSM_X4(Bh[nxt][0], Bh[nxt][1], Bh[nxt][2], Bh[nxt][3],
                        bh + offb[ks + 1]);
                LDSM_X4(Bl[nxt][0], Bl[nxt][1], Bl[nxt][2], Bl[nxt][3],
                        bl + offb[ks + 1]);
            }
            #pragma unroll
            for (int mt = 0; mt < 2; mt++)
                #pragma unroll
                for (int nt = 0; nt < 2; nt++)
                    MMA16816(d[mt][nt], Ah[cur][mt][0], Ah[cur][mt][1],
                             Ah[cur][mt][2], Ah[cur][mt][3],
                             Bh[cur][nt * 2], Bh[cur][nt * 2 + 1]);
            #pragma unroll
            for (int mt = 0; mt < 2; mt++)
                #pragma unroll
                for (int nt = 0; nt < 2; nt++)
                    MMA16816(d[mt][nt], Al[cur][mt][0], Al[cur][mt][1],
                             Al[cur][mt][2], Al[cur][mt][3],
                             Bh[cur][nt * 2], Bh[cur][nt * 2 + 1]);
            #pragma unroll
            for (int mt = 0; mt < 2; mt++)
                #pragma unroll
                for (int nt = 0; nt < 2; nt++)
                    MMA16816(d[mt][nt], Ah[cur][mt][0], Ah[cur][mt][1],
                             Ah[cur][mt][2], Ah[cur][mt][3],
                             Bl[cur][nt * 2], Bl[cur][nt * 2 + 1]);
        }
    }

    // ---- epilogue: logits (+bias) into smem (reuse pair buffers), softmax ----
    float* ls = (float*)sm;   // 32 rows x 256 cols f32 = 32KB
    __syncthreads();
    #pragma unroll
    for (int mt = 0; mt < 2; mt++) {
        int row = mt * 16 + (lane >> 2);
        #pragma unroll
        for (int nt = 0; nt < 2; nt++) {
            int col = wid * 16 + nt * 8 + (lane & 3) * 2;
            float2 bv = *(const float2*)(g_bias + col);
            float2 v0 = {d[mt][nt][0] + bv.x, d[mt][nt][1] + bv.y};
            float2 v1 = {d[mt][nt][2] + bv.x, d[mt][nt][3] + bv.y};
            *(float2*)(ls + row * NCLS + col)       = v0;
            *(float2*)(ls + (row + 8) * NCLS + col) = v1;
        }
    }
    __syncthreads();

    // warp handles rows wid*2, wid*2+1
    #pragma unroll
    for (int rr = 0; rr < 2; rr++) {
        int r = wid * 2 + rr;
        const float4* lrow = (const float4*)(ls + r * NCLS);
        float4 a = lrow[lane * 2];
        float4 b = lrow[lane * 2 + 1];

        float mx = fmaxf(fmaxf(fmaxf(a.x, a.y), fmaxf(a.z, a.w)),
                         fmaxf(fmaxf(b.x, b.y), fmaxf(b.z, b.w)));
        #pragma unroll
        for (int o = 16; o; o >>= 1) mx = fmaxf(mx, __shfl_xor_sync(0xFFFFFFFFu, mx, o));

        float4 ea, eb;
        ea.x = __expf(a.x - mx); ea.y = __expf(a.y - mx);
        ea.z = __expf(a.z - mx); ea.w = __expf(a.w - mx);
        eb.x = __expf(b.x - mx); eb.y = __expf(b.y - mx);
        eb.z = __expf(b.z - mx); eb.w = __expf(b.w - mx);

        float sum = (ea.x + ea.y) + (ea.z + ea.w) + (eb.x + eb.y) + (eb.z + eb.w);
        #pragma unroll
        for (int o = 16; o; o >>= 1) sum += __shfl_xor_sync(0xFFFFFFFFu, sum, o);

        float inv = 1.0f / sum;
        ea.x *= inv; ea.y *= inv; ea.z *= inv; ea.w *= inv;
        eb.x *= inv; eb.y *= inv; eb.z *= inv; eb.w *= inv;

        float4* orow = (float4*)(out + (size_t)(b0 + r) * NCLS);
        orow[lane * 2]     = ea;
        orow[lane * 2 + 1] = eb;
    }
}

// ---------------------------------------------------------------------------
extern "C" void kernel_launch(void* const* d_in, const int* in_sizes, int n_in,
                              void* d_out, int out_size) {
    const float* x       = (const float*)d_in[0];
    const float* centers = (const float*)d_in[1];
    const float* Droot   = (const float*)d_in[2];
    float*       out     = (float*)d_out;

    cudaFuncSetAttribute(gmm_fused_kernel,
                         cudaFuncAttributeMaxDynamicSharedMemorySize, SMEM_TOTAL);

    prep_w_kernel<<<NCLS, NDIM>>>(centers, Droot);
    gmm_fused_kernel<<<BATCH / MT, NTHR, SMEM_TOTAL>>>(x, out);
}